// round 2
// baseline (speedup 1.0000x reference)
#include <cuda_runtime.h>

typedef unsigned long long u64;

#define NHQ 16
#define HD  128
#define SEQ 2048
#define BM  128
#define BN  64
#define QSC 0.12751743f  /* (1/sqrt(128)) * log2(e) */

__device__ __forceinline__ u64 pkb(float x) {
  u64 r; unsigned xi = __float_as_uint(x);
  asm("mov.b64 %0, {%1,%2};" : "=l"(r) : "r"(xi), "r"(xi));
  return r;
}
__device__ __forceinline__ u64 f2fma(u64 a, u64 b, u64 c) {
  u64 d; asm("fma.rn.f32x2 %0, %1, %2, %3;" : "=l"(d) : "l"(a), "l"(b), "l"(c));
  return d;
}
__device__ __forceinline__ u64 f2mul(u64 a, u64 b) {
  u64 d; asm("mul.rn.f32x2 %0, %1, %2;" : "=l"(d) : "l"(a), "l"(b));
  return d;
}
__device__ __forceinline__ void upk(u64 v, float& x, float& y) {
  unsigned lo, hi; asm("mov.b64 {%0,%1}, %2;" : "=r"(lo), "=r"(hi) : "l"(v));
  x = __uint_as_float(lo); y = __uint_as_float(hi);
}
__device__ __forceinline__ float ex2(float x) {
  float y; asm("ex2.approx.ftz.f32 %0, %1;" : "=f"(y) : "f"(x)); return y;
}

extern __shared__ float sm[];

// SMEM (floats): Qt [128][130] at 0 (Q^T, d-major, pre-scaled);
//                Ks [64][130] at 16640 (K tile; reused as P [128][65]);
//                Vs [64][130] at 24960.  Total 33280 floats = 133120 B.
__global__ void __launch_bounds__(256, 1)
fa_kernel(const float* __restrict__ q, const float* __restrict__ k,
          const float* __restrict__ v, float* __restrict__ out) {
  float* Qt = sm;
  float* Ks = sm + 16640;
  float* Vs = sm + 24960;

  const int t  = threadIdx.x;
  const int tx = t & 15, ty = t >> 4;
  const int qt = 15 - (int)blockIdx.x;          // longest tiles first
  const int h  = blockIdx.y, b = blockIdx.z, hk = h >> 2;

  const float* qg = q + (size_t)(b * SEQ + qt * BM) * (NHQ * HD) + h * HD;
  const float* kg = k + (size_t)b * SEQ * 512 + hk * HD;
  const float* vg = v + (size_t)b * SEQ * 512 + hk * HD;

  // ---- Q load + scale + transpose into Qt[d][m] ----
  {
    const int lane = t & 31, w = t >> 5, d0 = lane * 4;
#pragma unroll
    for (int it = 0; it < 16; ++it) {
      const int m = w + it * 8;
      float4 val = *(const float4*)(qg + (size_t)m * (NHQ * HD) + d0);
      Qt[(d0 + 0) * 130 + m] = val.x * QSC;
      Qt[(d0 + 1) * 130 + m] = val.y * QSC;
      Qt[(d0 + 2) * 130 + m] = val.z * QSC;
      Qt[(d0 + 3) * 130 + m] = val.w * QSC;
    }
  }

  // Thread owns rows m = 2*ty + 32*p + e (8 rows) and out cols d = 2*tx + 32*r (+1).
  u64 O[8][4];
  float mr[8], lr[8];
#pragma unroll
  for (int im = 0; im < 8; ++im) {
    mr[im] = -1e30f; lr[im] = 0.f;
#pragma unroll
    for (int r = 0; r < 4; ++r) O[im][r] = 0ull;
  }

  const int nkt = 2 * qt + 2;
  for (int kt = 0; kt < nkt; ++kt) {
    __syncthreads();  // prev PV done reading Ks(P)/Vs; Qt ready on kt==0
    // ---- K,V tile load (coalesced float4 global -> float2 smem, stride 130) ----
    {
      const int lane = t & 31, w = t >> 5, d0 = lane * 4;
#pragma unroll
      for (int it = 0; it < 8; ++it) {
        const int n = w + it * 8;
        const size_t goff = (size_t)(kt * BN + n) * 512 + d0;
        float4 kf = *(const float4*)(kg + goff);
        float4 vf = *(const float4*)(vg + goff);
        float* kp = Ks + n * 130 + d0;
        float* vp = Vs + n * 130 + d0;
        *(float2*)kp       = make_float2(kf.x, kf.y);
        *(float2*)(kp + 2) = make_float2(kf.z, kf.w);
        *(float2*)vp       = make_float2(vf.x, vf.y);
        *(float2*)(vp + 2) = make_float2(vf.z, vf.w);
      }
    }
    __syncthreads();

    // ---- S = (Q*scale) K^T, packed over m-pairs; n = tx + 16*j ----
    u64 Sp[4][4];
#pragma unroll
    for (int mp = 0; mp < 4; ++mp)
#pragma unroll
      for (int j = 0; j < 4; ++j) Sp[mp][j] = 0ull;
    {
      const float* qrow = Qt + 2 * ty;
      const float* kb0  = Ks + tx * 130;
#pragma unroll 4
      for (int d = 0; d < 128; ++d) {
        u64 qp[4]; float kv4[4];
#pragma unroll
        for (int mp = 0; mp < 4; ++mp)
          qp[mp] = *(const u64*)(qrow + d * 130 + 32 * mp);
#pragma unroll
        for (int j = 0; j < 4; ++j) kv4[j] = kb0[j * (16 * 130) + d];
#pragma unroll
        for (int mp = 0; mp < 4; ++mp)
#pragma unroll
          for (int j = 0; j < 4; ++j)
            Sp[mp][j] = f2fma(qp[mp], pkb(kv4[j]), Sp[mp][j]);
      }
    }

    // ---- unpack + causal mask + online softmax (base-2) ----
    float sv[8][4];
#pragma unroll
    for (int mp = 0; mp < 4; ++mp)
#pragma unroll
      for (int j = 0; j < 4; ++j)
        upk(Sp[mp][j], sv[2 * mp][j], sv[2 * mp + 1][j]);

    if (kt >= 2 * qt) {  // only the last two kv tiles cross the diagonal
#pragma unroll
      for (int im = 0; im < 8; ++im) {
        const int mG = qt * BM + 2 * ty + 32 * (im >> 1) + (im & 1);
#pragma unroll
        for (int j = 0; j < 4; ++j)
          if (kt * BN + tx + 16 * j > mG) sv[im][j] = -1e30f;
      }
    }

    float pc[8];
#pragma unroll
    for (int im = 0; im < 8; ++im) {
      float mx = fmaxf(fmaxf(sv[im][0], sv[im][1]), fmaxf(sv[im][2], sv[im][3]));
      mx = fmaxf(mx, __shfl_xor_sync(0xffffffffu, mx, 1));
      mx = fmaxf(mx, __shfl_xor_sync(0xffffffffu, mx, 2));
      mx = fmaxf(mx, __shfl_xor_sync(0xffffffffu, mx, 4));
      mx = fmaxf(mx, __shfl_xor_sync(0xffffffffu, mx, 8));
      const float mn = fmaxf(mr[im], mx);
      pc[im] = ex2(mr[im] - mn);
      mr[im] = mn;
      float rs = 0.f;
#pragma unroll
      for (int j = 0; j < 4; ++j) {
        const float p = ex2(sv[im][j] - mn);
        sv[im][j] = p;
        rs += p;
      }
      rs += __shfl_xor_sync(0xffffffffu, rs, 1);
      rs += __shfl_xor_sync(0xffffffffu, rs, 2);
      rs += __shfl_xor_sync(0xffffffffu, rs, 4);
      rs += __shfl_xor_sync(0xffffffffu, rs, 8);
      lr[im] = lr[im] * pc[im] + rs;
    }
#pragma unroll
    for (int im = 0; im < 8; ++im) {
      const u64 cb = pkb(pc[im]);
#pragma unroll
      for (int r = 0; r < 4; ++r) O[im][r] = f2mul(O[im][r], cb);
    }

    __syncthreads();  // all S reads of Ks done before overwriting with P
#pragma unroll
    for (int im = 0; im < 8; ++im) {
      const int m = 2 * ty + 32 * (im >> 1) + (im & 1);
#pragma unroll
      for (int j = 0; j < 4; ++j)
        Ks[m * 65 + tx + 16 * j] = sv[im][j];
    }
    __syncthreads();  // P visible

    // ---- O += P V, packed over d-pairs ----
    {
      const float* pb = Ks + 2 * ty * 65;
      const float* vb = Vs + 2 * tx;
#pragma unroll 2
      for (int n = 0; n < 64; ++n) {
        u64 vv[4];
#pragma unroll
        for (int r = 0; r < 4; ++r)
          vv[r] = *(const u64*)(vb + n * 130 + 32 * r);
        float pv[8];
#pragma unroll
        for (int im = 0; im < 8; ++im)
          pv[im] = pb[(32 * (im >> 1) + (im & 1)) * 65 + n];
#pragma unroll
        for (int im = 0; im < 8; ++im) {
          const u64 pbr = pkb(pv[im]);
#pragma unroll
          for (int r = 0; r < 4; ++r)
            O[im][r] = f2fma(pbr, vv[r], O[im][r]);
        }
      }
    }
  }

  // ---- epilogue: O /= l, coalesced float2 stores ----
#pragma unroll
  for (int im = 0; im < 8; ++im) {
    const u64 ib = pkb(1.0f / lr[im]);
    const int m  = 2 * ty + 32 * (im >> 1) + (im & 1);
    float* og = out + (size_t)(b * SEQ + qt * BM + m) * (NHQ * HD) + h * HD + 2 * tx;
#pragma unroll
    for (int r = 0; r < 4; ++r)
      *(u64*)(og + 32 * r) = f2mul(O[im][r], ib);
  }
}

extern "C" void kernel_launch(void* const* d_in, const int* in_sizes, int n_in,
                              void* d_out, int out_size) {
  const float* q = (const float*)d_in[0];
  const float* k = (const float*)d_in[1];
  const float* v = (const float*)d_in[2];
  float* out = (float*)d_out;
  (void)in_sizes; (void)n_in; (void)out_size;
  cudaFuncSetAttribute(fa_kernel, cudaFuncAttributeMaxDynamicSharedMemorySize, 133120);
  fa_kernel<<<dim3(16, 16, 4), 256, 133120>>>(q, k, v, out);
}